// round 16
// baseline (speedup 1.0000x reference)
#include <cuda_runtime.h>
#include <cuda_bf16.h>
#include <math.h>

#define Nn 10000
#define Hh 512
#define Tt 4
#define Ee 40000
#define Ll 2
#define G3 (3*Hh)
#define TN (Tt*Nn)
#define PW (Tt*Hh)            // 2048
#define WMSG_SZ (Ll*Tt*Hh*Hh)
#define WIH_SZ  (Ll*G3*Hh)
#define FC_SZ   (Hh*Hh)
#define MBLK 79

typedef unsigned long long u64;
typedef unsigned int u32;
typedef __nv_bfloat16 bf;

// ---------------- device scratch ----------------
__device__ __align__(16) float g_h  [2*(size_t)Nn*Hh];
__device__ __align__(16) float g_P  [(size_t)Nn*PW];
__device__ __align__(16) float g_gi [(size_t)Nn*G3];
__device__ __align__(16) float g_gh [(size_t)Nn*G3];
__device__ __align__(16) float g_pm [100*Hh];
__device__ __align__(16) bf g_ihi[(size_t)Nn*Hh];
__device__ __align__(16) bf g_ilo[(size_t)Nn*Hh];
__device__ __align__(16) bf g_hhi[(size_t)Nn*Hh];
__device__ __align__(16) bf g_hlo[(size_t)Nn*Hh];
__device__ __align__(16) bf g_Wmh[WMSG_SZ];
__device__ __align__(16) bf g_Wml[WMSG_SZ];
__device__ __align__(16) bf g_Wih[WIH_SZ];
__device__ __align__(16) bf g_Wil[WIH_SZ];
__device__ __align__(16) bf g_Whh[WIH_SZ];
__device__ __align__(16) bf g_Whl[WIH_SZ];
__device__ __align__(16) bf g_fch[FC_SZ];
__device__ __align__(16) bf g_fcl[FC_SZ];
__device__ int g_deg [TN];
__device__ int g_off [TN + 1];
__device__ int g_cur [TN];
__device__ int g_csr [Tt*Ee];
__device__ int g_bsum[64];
__device__ int g_bofs[64];

// ---------------- smem geometry ----------------
#define TILE_SZ 16384
#define BUFSZ   (2*TILE_SZ)
#define NSTAGE  3
#define SMEM_BYTES (NSTAGE*BUFSZ)

__device__ __forceinline__ u32 smem_u32(const void* p) {
    u32 a;
    asm("{ .reg .u64 t; cvta.to.shared.u64 t, %1; cvt.u32.u64 %0, t; }" : "=r"(a) : "l"(p));
    return a;
}
__device__ __forceinline__ void ldsm4(u32 r[4], u32 addr) {
    asm volatile("ldmatrix.sync.aligned.m8n8.x4.shared.b16 {%0,%1,%2,%3}, [%4];"
                 : "=r"(r[0]), "=r"(r[1]), "=r"(r[2]), "=r"(r[3]) : "r"(addr));
}
__device__ __forceinline__ void mma16816(float d[4], const u32 a[4], u32 b0, u32 b1) {
    asm volatile("mma.sync.aligned.m16n8k16.row.col.f32.bf16.bf16.f32 "
                 "{%0,%1,%2,%3}, {%4,%5,%6,%7}, {%8,%9}, {%0,%1,%2,%3};"
                 : "+f"(d[0]), "+f"(d[1]), "+f"(d[2]), "+f"(d[3])
                 : "r"(a[0]), "r"(a[1]), "r"(a[2]), "r"(a[3]), "r"(b0), "r"(b1));
}
__device__ __forceinline__ void split1(float v, bf& h, bf& l) {
    h = __float2bfloat16(v);
    l = __float2bfloat16(v - __bfloat162float(h));
}
__device__ __forceinline__ void cpa16(u32 saddr, const void* g) {
    asm volatile("cp.async.cg.shared.global [%0], [%1], 16;" :: "r"(saddr), "l"(g) : "memory");
}
#define CPA_COMMIT() asm volatile("cp.async.commit_group;" ::: "memory")
#define CPA_WAIT1()  asm volatile("cp.async.wait_group 1;" ::: "memory")

__device__ __forceinline__ u32 tswz(int row, int lc) {
    return (u32)(row * 128 + ((lc ^ (row & 7)) << 4));
}
__device__ __forceinline__ void cpa_tile2(const bf* __restrict__ hi, const bf* __restrict__ lo,
                                          int rowMax, int r0, int tid, u32 sdst) {
#pragma unroll
    for (int i = 0; i < 4; i++) {
        int c = i * 256 + tid;
        int row = c >> 3;
        int lc  = c & 7;
        int m = r0 + row;
        if (m >= rowMax) m = rowMax - 1;
        const bf* src = (lc < 4) ? hi + (size_t)m * Hh + lc * 8
                                 : lo + (size_t)m * Hh + (lc - 4) * 8;
        cpa16(sdst + tswz(row, lc), src);
    }
}

__device__ __forceinline__ float fsig(float x)  { return 1.f / (1.f + __expf(-x)); }
__device__ __forceinline__ float ftanh(float x) { return 2.f / (1.f + __expf(-2.f * x)) - 1.f; }

// ============ GEMM body: C[M,Nout](+bias) = A[M,512] * B[Nout,512]^T ============
// B pointers are BASE pointers; row offset comes ONLY from n0.
__device__ __forceinline__ void gemm_body(
    const bf* __restrict__ Ahi, const bf* __restrict__ Alo,
    const bf* __restrict__ Bhi, const bf* __restrict__ Blo,
    const float* __restrict__ bias, float* __restrict__ C,
    int M, int Nout, int m0, int n0, char* smem)
{
    const int tid = threadIdx.x;
    const int lane = tid & 31, wid = tid >> 5;
    const int wm = wid & 3, wn = wid >> 2;
    u32 sb = smem_u32(smem);

    float acc[2][8][4];
#pragma unroll
    for (int i = 0; i < 2; i++)
#pragma unroll
        for (int j = 0; j < 8; j++)
#pragma unroll
            for (int k = 0; k < 4; k++) acc[i][j][k] = 0.f;

#pragma unroll
    for (int s = 0; s < 2; s++) {
        int koff = s * 32;
        u32 dst = sb + s * BUFSZ;
        cpa_tile2(Ahi + koff, Alo + koff, M, m0, tid, dst);
        cpa_tile2(Bhi + koff, Blo + koff, 1 << 30, n0, tid, dst + TILE_SZ);
        CPA_COMMIT();
    }

    int buf = 0;
    for (int kb = 0; kb < 16; kb++) {
        CPA_WAIT1();
        __syncthreads();

        if (kb + 2 < 16) {
            int koff = (kb + 2) * 32;
            int bn = buf + 2; if (bn >= NSTAGE) bn -= NSTAGE;
            u32 dst = sb + bn * BUFSZ;
            cpa_tile2(Ahi + koff, Alo + koff, M, m0, tid, dst);
            cpa_tile2(Bhi + koff, Blo + koff, 1 << 30, n0, tid, dst + TILE_SZ);
        }
        CPA_COMMIT();

        u32 aT = sb + buf * BUFSZ;
        u32 bT = aT + TILE_SZ;
#pragma unroll
        for (int ks = 0; ks < 2; ks++) {
            int lcA = 2 * ks + (lane >> 4);
            u32 ah[2][4], al[2][4];
#pragma unroll
            for (int mt = 0; mt < 2; mt++) {
                int row = wm * 32 + mt * 16 + (lane & 15);
                ldsm4(ah[mt], aT + tswz(row, lcA));
                ldsm4(al[mt], aT + tswz(row, lcA + 4));
            }
#pragma unroll
            for (int half = 0; half < 2; half++) {
                u32 bh[2][4], bl[2][4];
#pragma unroll
                for (int np = 0; np < 2; np++) {
                    int np2 = half * 2 + np;
                    int row = wn * 64 + np2 * 16 + (lane & 7) + ((lane >> 3) & 1) * 8;
                    ldsm4(bh[np], bT + tswz(row, lcA));
                    ldsm4(bl[np], bT + tswz(row, lcA + 4));
                }
#pragma unroll
                for (int mt = 0; mt < 2; mt++)
#pragma unroll
                    for (int j = 0; j < 4; j++) {
                        int np = j >> 1, sub = j & 1;
                        int nt = half * 4 + j;
                        mma16816(acc[mt][nt], ah[mt], bh[np][sub], bh[np][sub + 2]);
                        mma16816(acc[mt][nt], ah[mt], bl[np][sub], bl[np][sub + 2]);
                        mma16816(acc[mt][nt], al[mt], bh[np][sub], bh[np][sub + 2]);
                    }
            }
        }
        buf++; if (buf >= NSTAGE) buf = 0;
    }

    __syncthreads();

#pragma unroll
    for (int mt = 0; mt < 2; mt++) {
        int rbase = m0 + wm * 32 + mt * 16 + (lane >> 2);
#pragma unroll
        for (int half = 0; half < 2; half++) {
            int r = rbase + half * 8;
            if (r >= M) continue;
#pragma unroll
            for (int nt = 0; nt < 8; nt++) {
                int col = n0 + wn * 64 + nt * 8 + (lane & 3) * 2;
                float v0 = acc[mt][nt][half * 2 + 0];
                float v1 = acc[mt][nt][half * 2 + 1];
                if (bias) {
                    float2 b = *reinterpret_cast<const float2*>(bias + col);
                    v0 += b.x; v1 += b.y;
                }
                *reinterpret_cast<float2*>(C + (size_t)r * Nout + col) = make_float2(v0, v1);
            }
        }
    }
}

// ============ L1: P GEMM (y<16) + gh GEMM (y>=16), same A operand ============
__global__ __launch_bounds__(256, 2)
void k_big(const bf* __restrict__ hhi, const bf* __restrict__ hlo,
           const bf* __restrict__ Wmh, const bf* __restrict__ Wml,
           float* __restrict__ P,
           const bf* __restrict__ Whh, const bf* __restrict__ Whl,
           const float* __restrict__ bhh, float* __restrict__ gh)
{
    extern __shared__ __align__(16) char smem[];
    int y = blockIdx.y;
    if (y < 16) {
        gemm_body(hhi, hlo, Wmh, Wml, nullptr, P,
                  Nn, PW, blockIdx.x * 128, y * 128, smem);
    } else {
        gemm_body(hhi, hlo, Whh, Whl, bhh, gh,
                  Nn, G3, blockIdx.x * 128, (y - 16) * 128, smem);
    }
}

// generic GEMM (gi, fc) — base B pointer, n0 from blockIdx.y
__global__ __launch_bounds__(256, 2)
void mma_gemm(const bf* __restrict__ Ahi, const bf* __restrict__ Alo,
              const bf* __restrict__ Bhi, const bf* __restrict__ Blo,
              const float* __restrict__ bias, float* __restrict__ C,
              int M, int Nout)
{
    extern __shared__ __align__(16) char smem[];
    gemm_body(Ahi, Alo, Bhi, Blo, bias, C,
              M, Nout, blockIdx.x * 128, blockIdx.y * 128, smem);
}

// ---------------- aggregation over P ----------------
__device__ __forceinline__ void st4_split(bf* hi, bf* lo, float4 a) {
    bf h0,l0,h1,l1,h2,l2,h3,l3;
    split1(a.x, h0, l0); split1(a.y, h1, l1);
    split1(a.z, h2, l2); split1(a.w, h3, l3);
    *reinterpret_cast<__nv_bfloat162*>(hi)     = __nv_bfloat162(h0, h1);
    *reinterpret_cast<__nv_bfloat162*>(hi + 2) = __nv_bfloat162(h2, h3);
    *reinterpret_cast<__nv_bfloat162*>(lo)     = __nv_bfloat162(l0, l1);
    *reinterpret_cast<__nv_bfloat162*>(lo + 2) = __nv_bfloat162(l2, l3);
}
__device__ __forceinline__ void acc4(float4& a, float4 v) {
    a.x += v.x; a.y += v.y; a.z += v.z; a.w += v.w;
}
__device__ __forceinline__ void acc4s(float4& a, float s, float4 v) {
    a.x += s * v.x; a.y += s * v.y; a.z += s * v.z; a.w += s * v.w;
}
__global__ void agg_p(const float* __restrict__ P, const int* __restrict__ csr,
                      const int* __restrict__ off, const float* __restrict__ bm,
                      bf* __restrict__ iHi, bf* __restrict__ iLo) {
    int node = (blockIdx.x * blockDim.x + threadIdx.x) >> 5;
    int lane = threadIdx.x & 31;
    if (node >= Nn) return;
    float4 a0 = make_float4(0.f,0.f,0.f,0.f), a1 = a0, a2 = a0, a3 = a0;
#pragma unroll
    for (int t = 0; t < Tt; t++) {
        int r = t * Nn + node;
        int s = off[r], e = off[r + 1];
        int i = s;
        for (; i + 2 <= e; i += 2) {
            const float4* p0 = reinterpret_cast<const float4*>(
                P + (size_t)__ldg(csr + i)     * PW + t * Hh);
            const float4* p1 = reinterpret_cast<const float4*>(
                P + (size_t)__ldg(csr + i + 1) * PW + t * Hh);
            acc4(a0, p0[lane]);    acc4(a0, p1[lane]);
            acc4(a1, p0[lane+32]); acc4(a1, p1[lane+32]);
            acc4(a2, p0[lane+64]); acc4(a2, p1[lane+64]);
            acc4(a3, p0[lane+96]); acc4(a3, p1[lane+96]);
        }
        if (i < e) {
            const float4* p0 = reinterpret_cast<const float4*>(
                P + (size_t)__ldg(csr + i) * PW + t * Hh);
            acc4(a0, p0[lane]); acc4(a1, p0[lane+32]);
            acc4(a2, p0[lane+64]); acc4(a3, p0[lane+96]);
        }
        float d = (float)(e - s);
        const float4* bmp = reinterpret_cast<const float4*>(bm + t * Hh);
        acc4s(a0, d, bmp[lane]);    acc4s(a1, d, bmp[lane+32]);
        acc4s(a2, d, bmp[lane+64]); acc4s(a3, d, bmp[lane+96]);
    }
    bf* Hp = iHi + (size_t)node * Hh;
    bf* Lp = iLo + (size_t)node * Hh;
    st4_split(Hp + lane * 4,        Lp + lane * 4,        a0);
    st4_split(Hp + (lane + 32) * 4, Lp + (lane + 32) * 4, a1);
    st4_split(Hp + (lane + 64) * 4, Lp + (lane + 64) * 4, a2);
    st4_split(Hp + (lane + 96) * 4, Lp + (lane + 96) * 4, a3);
}

// ---------------- fused init ----------------
__global__ void init_all(const float* __restrict__ x,
                         const float* __restrict__ W_msg, const float* __restrict__ W_ih,
                         const float* __restrict__ W_hh,  const float* __restrict__ fc_W,
                         float* __restrict__ h,
                         bf* __restrict__ hhi, bf* __restrict__ hlo,
                         bf* __restrict__ Wmh, bf* __restrict__ Wml,
                         bf* __restrict__ Wih, bf* __restrict__ Wil,
                         bf* __restrict__ Whh, bf* __restrict__ Whl,
                         bf* __restrict__ fch, bf* __restrict__ fcl) {
    const int R0 = Nn * Hh / 4;
    const int R1 = R0 + WMSG_SZ / 4;
    const int R2 = R1 + WIH_SZ / 4;
    const int R3 = R2 + WIH_SZ / 4;
    const int R4 = R3 + FC_SZ / 4;
    int i = blockIdx.x * blockDim.x + threadIdx.x;
    int stride = gridDim.x * blockDim.x;
    for (; i < R4; i += stride) {
        const float* src; bf* hi; bf* lo; int k; bool cp = false;
        if (i < R0)      { src = x;     hi = hhi; lo = hlo; k = i;      cp = true; }
        else if (i < R1) { src = W_msg; hi = Wmh; lo = Wml; k = i - R0; }
        else if (i < R2) { src = W_ih;  hi = Wih; lo = Wil; k = i - R1; }
        else if (i < R3) { src = W_hh;  hi = Whh; lo = Whl; k = i - R2; }
        else             { src = fc_W;  hi = fch; lo = fcl; k = i - R3; }
        float4 v = reinterpret_cast<const float4*>(src)[k];
        if (cp) reinterpret_cast<float4*>(h)[k] = v;
        bf h0,l0,h1,l1,h2,l2,h3,l3;
        split1(v.x, h0, l0); split1(v.y, h1, l1);
        split1(v.z, h2, l2); split1(v.w, h3, l3);
        *reinterpret_cast<__nv_bfloat162*>(hi + k*4)     = __nv_bfloat162(h0, h1);
        *reinterpret_cast<__nv_bfloat162*>(hi + k*4 + 2) = __nv_bfloat162(h2, h3);
        *reinterpret_cast<__nv_bfloat162*>(lo + k*4)     = __nv_bfloat162(l0, l1);
        *reinterpret_cast<__nv_bfloat162*>(lo + k*4 + 2) = __nv_bfloat162(l2, l3);
    }
}

__global__ void zero2_i(int* p, int* q, int n) {
    int i = blockIdx.x * blockDim.x + threadIdx.x;
    if (i < n) { p[i] = 0; q[i] = 0; }
}
__global__ void count_deg(const int* __restrict__ edges, int* __restrict__ deg) {
    int idx = blockIdx.x * blockDim.x + threadIdx.x;
    if (idx < Tt * Ee) {
        int t = idx / Ee;
        int tgt = edges[idx * 2 + 1];
        atomicAdd(&deg[t * Nn + tgt], 1);
    }
}

// ---------------- CSR build ----------------
__global__ void scan1(const int* __restrict__ deg, int* __restrict__ off, int* __restrict__ bsum) {
    __shared__ int sm[1024];
    int t = threadIdx.x;
    int i = blockIdx.x * 1024 + t;
    int v = (i < TN) ? deg[i] : 0;
    sm[t] = v;
    __syncthreads();
    for (int d = 1; d < 1024; d <<= 1) {
        int x = (t >= d) ? sm[t - d] : 0;
        __syncthreads();
        sm[t] += x;
        __syncthreads();
    }
    if (i < TN) off[i + 1] = sm[t];
    if (t == 1023) bsum[blockIdx.x] = sm[t];
}
__global__ void scan2(const int* __restrict__ bsum, int* __restrict__ bofs, int nb) {
    __shared__ int sm[64];
    int t = threadIdx.x;
    int v = (t < nb) ? bsum[t] : 0;
    sm[t] = v;
    __syncthreads();
    for (int d = 1; d < 64; d <<= 1) {
        int x = (t >= d) ? sm[t - d] : 0;
        __syncthreads();
        sm[t] += x;
        __syncthreads();
    }
    bofs[t] = sm[t] - v;
}
__global__ void scan3(int* __restrict__ off, const int* __restrict__ bofs) {
    int i = blockIdx.x * blockDim.x + threadIdx.x;
    if (i == 0) off[0] = 0;
    if (i < TN) off[i + 1] += bofs[i >> 10];
}
__global__ void scatter_csr(const int* __restrict__ edges, const int* __restrict__ off,
                            int* __restrict__ cur, int* __restrict__ csr) {
    int idx = blockIdx.x * blockDim.x + threadIdx.x;
    if (idx >= Tt * Ee) return;
    int t = idx / Ee;
    int src = edges[idx * 2 + 0];
    int tgt = edges[idx * 2 + 1];
    int r = t * Nn + tgt;
    int p = off[r] + atomicAdd(&cur[r], 1);
    csr[p] = src;
}

// ---------------- GRU elementwise ----------------
__global__ void gru_kernel(const float* __restrict__ gi, const float* __restrict__ gh,
                           const float* __restrict__ h, float* __restrict__ hout,
                           bf* __restrict__ hhi, bf* __restrict__ hlo) {
    int idx4 = blockIdx.x * blockDim.x + threadIdx.x;
    if (idx4 >= Nn * Hh / 4) return;
    int n = idx4 >> 7;
    int j4 = idx4 & 127;
    size_t base = ((size_t)n * G3 + j4 * 4) >> 2;
    const float4* gi4 = reinterpret_cast<const float4*>(gi);
    const float4* gh4 = reinterpret_cast<const float4*>(gh);
    float4 ir = gi4[base],        hr = gh4[base];
    float4 iz = gi4[base + 128],  hz = gh4[base + 128];
    float4 in_ = gi4[base + 256], hn = gh4[base + 256];
    float4 hv = reinterpret_cast<const float4*>(h)[idx4];
    float o[4];
    float irA[4] = {ir.x, ir.y, ir.z, ir.w}, hrA[4] = {hr.x, hr.y, hr.z, hr.w};
    float izA[4] = {iz.x, iz.y, iz.z, iz.w}, hzA[4] = {hz.x, hz.y, hz.z, hz.w};
    float inA[4] = {in_.x, in_.y, in_.z, in_.w}, hnA[4] = {hn.x, hn.y, hn.z, hn.w};
    float hA[4]  = {hv.x, hv.y, hv.z, hv.w};
#pragma unroll
    for (int q = 0; q < 4; q++) {
        float r = fsig(irA[q] + hrA[q]);
        float z = fsig(izA[q] + hzA[q]);
        float nv = ftanh(inA[q] + r * hnA[q]);
        o[q] = (1.f - z) * nv + z * hA[q];
    }
    reinterpret_cast<float4*>(hout)[idx4] = make_float4(o[0], o[1], o[2], o[3]);
    bf h0,l0,h1,l1,h2,l2,h3,l3;
    split1(o[0], h0, l0); split1(o[1], h1, l1);
    split1(o[2], h2, l2); split1(o[3], h3, l3);
    *reinterpret_cast<__nv_bfloat162*>(hhi + idx4*4)     = __nv_bfloat162(h0, h1);
    *reinterpret_cast<__nv_bfloat162*>(hhi + idx4*4 + 2) = __nv_bfloat162(h2, h3);
    *reinterpret_cast<__nv_bfloat162*>(hlo + idx4*4)     = __nv_bfloat162(l0, l1);
    *reinterpret_cast<__nv_bfloat162*>(hlo + idx4*4 + 2) = __nv_bfloat162(l2, l3);
}

// ---------------- column max ----------------
__global__ void pmax_kernel(const float* __restrict__ X, float* __restrict__ pm) {
    int k = threadIdx.x;
    int b = blockIdx.x;
    float m = -INFINITY;
    int r0 = b * 100;
    for (int r = 0; r < 100; r++)
        m = fmaxf(m, X[(size_t)(r0 + r) * Hh + k]);
    pm[b * Hh + k] = m;
}
__global__ void fmax_kernel(const float* __restrict__ pm, float* __restrict__ out) {
    int k = threadIdx.x;
    float m = -INFINITY;
    for (int b = 0; b < 100; b++)
        m = fmaxf(m, pm[b * Hh + k]);
    out[k] = m;
}

// ---------------- launch ----------------
extern "C" void kernel_launch(void* const* d_in, const int* in_sizes, int n_in,
                              void* d_out, int out_size) {
    const float* x     = (const float*)d_in[0];
    const int*   edges = (const int*)  d_in[1];
    const float* W_msg = (const float*)d_in[2];
    const float* b_msg = (const float*)d_in[3];
    const float* W_ih  = (const float*)d_in[4];
    const float* W_hh  = (const float*)d_in[5];
    const float* b_ih  = (const float*)d_in[6];
    const float* b_hh  = (const float*)d_in[7];
    const float* fc_W  = (const float*)d_in[8];
    const float* fc_b  = (const float*)d_in[9];
    float* out = (float*)d_out;

    float *ph, *pP, *pgi, *pgh, *ppm;
    bf *pihi, *pilo, *phhi, *phlo;
    bf *pWmh, *pWml, *pWih, *pWil, *pWhh, *pWhl, *pfch, *pfcl;
    int *pdeg, *poff, *pcur, *pcsr, *pbsum, *pbofs;
    cudaGetSymbolAddress((void**)&ph,    g_h);
    cudaGetSymbolAddress((void**)&pP,    g_P);
    cudaGetSymbolAddress((void**)&pgi,   g_gi);
    cudaGetSymbolAddress((void**)&pgh,   g_gh);
    cudaGetSymbolAddress((void**)&ppm,   g_pm);
    cudaGetSymbolAddress((void**)&pihi,  g_ihi);
    cudaGetSymbolAddress((void**)&pilo,  g_ilo);
    cudaGetSymbolAddress((void**)&phhi,  g_hhi);
    cudaGetSymbolAddress((void**)&phlo,  g_hlo);
    cudaGetSymbolAddress((void**)&pWmh,  g_Wmh);
    cudaGetSymbolAddress((void**)&pWml,  g_Wml);
    cudaGetSymbolAddress((void**)&pWih,  g_Wih);
    cudaGetSymbolAddress((void**)&pWil,  g_Wil);
    cudaGetSymbolAddress((void**)&pWhh,  g_Whh);
    cudaGetSymbolAddress((void**)&pWhl,  g_Whl);
    cudaGetSymbolAddress((void**)&pfch,  g_fch);
    cudaGetSymbolAddress((void**)&pfcl,  g_fcl);
    cudaGetSymbolAddress((void**)&pdeg,  g_deg);
    cudaGetSymbolAddress((void**)&poff,  g_off);
    cudaGetSymbolAddress((void**)&pcur,  g_cur);
    cudaGetSymbolAddress((void**)&pcsr,  g_csr);
    cudaGetSymbolAddress((void**)&pbsum, g_bsum);
    cudaGetSymbolAddress((void**)&pbofs, g_bofs);

    cudaFuncSetAttribute(mma_gemm, cudaFuncAttributeMaxDynamicSharedMemorySize, SMEM_BYTES);
    cudaFuncSetAttribute(k_big,    cudaFuncAttributeMaxDynamicSharedMemorySize, SMEM_BYTES);

    float* hc = ph;
    float* hn = ph + (size_t)Nn * Hh;

    init_all<<<4096, 256>>>(x, W_msg, W_ih, W_hh, fc_W, hc,
                            phhi, phlo, pWmh, pWml, pWih, pWil, pWhh, pWhl, pfch, pfcl);

    zero2_i<<<(TN + 255) / 256, 256>>>(pdeg, pcur, TN);
    count_deg<<<(Tt * Ee + 255) / 256, 256>>>(edges, pdeg);
    scan1<<<(TN + 1023) / 1024, 1024>>>(pdeg, poff, pbsum);
    scan2<<<1, 64>>>(pbsum, pbofs, (TN + 1023) / 1024);
    scan3<<<(TN + 255) / 256, 256>>>(poff, pbofs);
    scatter_csr<<<(Tt * Ee + 255) / 256, 256>>>(edges, poff, pcur, pcsr);

    dim3 gBig(MBLK, 28);       // 16 P-tiles + 12 gh-tiles
    dim3 gGi(MBLK, G3 / 128);
    dim3 gFc(MBLK, Hh / 128);
    int aggBlocks = (Nn * 32 + 255) / 256;

    for (int layer = 0; layer < Ll; layer++) {
        const bf* Wmh_l = pWmh + (size_t)layer * Tt * Hh * Hh;
        const bf* Wml_l = pWml + (size_t)layer * Tt * Hh * Hh;
        const bf* Wih_l = pWih + (size_t)layer * G3 * Hh;
        const bf* Wil_l = pWil + (size_t)layer * G3 * Hh;
        const bf* Whh_l = pWhh + (size_t)layer * G3 * Hh;
        const bf* Whl_l = pWhl + (size_t)layer * G3 * Hh;
        const float* bm_l  = b_msg + (size_t)layer * Tt * Hh;
        const float* bih_l = b_ih  + (size_t)layer * G3;
        const float* bhh_l = b_hh  + (size_t)layer * G3;
        for (int s = 0; s < 2; s++) {
            k_big<<<gBig, 256, SMEM_BYTES>>>(phhi, phlo, Wmh_l, Wml_l, pP,
                                             Whh_l, Whl_l, bhh_l, pgh);
            agg_p<<<aggBlocks, 256>>>(pP, pcsr, poff, bm_l, pihi, pilo);
            mma_gemm<<<gGi, 256, SMEM_BYTES>>>(pihi, pilo, Wih_l, Wil_l, bih_l, pgi, Nn, G3);
            gru_kernel<<<(Nn * Hh / 4 + 255) / 256, 256>>>(pgi, pgh, hc, hn, phhi, phlo);
            float* t = hc; hc = hn; hn = t;
        }
    }

    mma_gemm<<<gFc, 256, SMEM_BYTES>>>(phhi, phlo, pfch, pfcl, fc_b, pgi, Nn, Hh);
    pmax_kernel<<<100, 512>>>(pgi, ppm);
    fmax_kernel<<<1, 512>>>(ppm, out);
}

// round 17
// speedup vs baseline: 1.0392x; 1.0392x over previous
#include <cuda_runtime.h>
#include <cuda_bf16.h>
#include <math.h>

#define Nn 10000
#define Hh 512
#define Tt 4
#define Ee 40000
#define Ll 2
#define G3 (3*Hh)
#define TN (Tt*Nn)
#define WMSG_SZ (Ll*Tt*Hh*Hh)
#define WIH_SZ  (Ll*G3*Hh)
#define FC_SZ   (Hh*Hh)
#define MBLK 79

typedef unsigned long long u64;
typedef unsigned int u32;
typedef __nv_bfloat16 bf;

// ---------------- device scratch ----------------
__device__ __align__(16) float g_h  [2*(size_t)Nn*Hh];
__device__ __align__(16) float g_gi [(size_t)Nn*G3];
__device__ __align__(16) float g_gh [(size_t)Nn*G3];
__device__ __align__(16) bf g_Shi[(size_t)TN*Hh];
__device__ __align__(16) bf g_Slo[(size_t)TN*Hh];
__device__ __align__(16) bf g_ihi[(size_t)Nn*Hh];
__device__ __align__(16) bf g_ilo[(size_t)Nn*Hh];
__device__ __align__(16) bf g_hhi[(size_t)Nn*Hh];
__device__ __align__(16) bf g_hlo[(size_t)Nn*Hh];
__device__ __align__(16) bf g_Wmh[WMSG_SZ];
__device__ __align__(16) bf g_Wml[WMSG_SZ];
__device__ __align__(16) bf g_Wih[WIH_SZ];
__device__ __align__(16) bf g_Wil[WIH_SZ];
__device__ __align__(16) bf g_Whh[WIH_SZ];
__device__ __align__(16) bf g_Whl[WIH_SZ];
__device__ __align__(16) bf g_fch[FC_SZ];
__device__ __align__(16) bf g_fcl[FC_SZ];
__device__ int g_deg [TN];
__device__ int g_off [TN + 1];
__device__ int g_cur [TN];
__device__ int g_csr [Tt*Ee];
__device__ int g_bsum[64];
__device__ int g_bofs[64];

// ---------------- smem geometry ----------------
#define TILE_SZ 16384
#define BUFSZ   (2*TILE_SZ)
#define NSTAGE  3
#define SMEM_BYTES (NSTAGE*BUFSZ)

__device__ __forceinline__ u32 smem_u32(const void* p) {
    u32 a;
    asm("{ .reg .u64 t; cvta.to.shared.u64 t, %1; cvt.u32.u64 %0, t; }" : "=r"(a) : "l"(p));
    return a;
}
__device__ __forceinline__ void ldsm4(u32 r[4], u32 addr) {
    asm volatile("ldmatrix.sync.aligned.m8n8.x4.shared.b16 {%0,%1,%2,%3}, [%4];"
                 : "=r"(r[0]), "=r"(r[1]), "=r"(r[2]), "=r"(r[3]) : "r"(addr));
}
__device__ __forceinline__ void mma16816(float d[4], const u32 a[4], u32 b0, u32 b1) {
    asm volatile("mma.sync.aligned.m16n8k16.row.col.f32.bf16.bf16.f32 "
                 "{%0,%1,%2,%3}, {%4,%5,%6,%7}, {%8,%9}, {%0,%1,%2,%3};"
                 : "+f"(d[0]), "+f"(d[1]), "+f"(d[2]), "+f"(d[3])
                 : "r"(a[0]), "r"(a[1]), "r"(a[2]), "r"(a[3]), "r"(b0), "r"(b1));
}
__device__ __forceinline__ void split1(float v, bf& h, bf& l) {
    h = __float2bfloat16(v);
    l = __float2bfloat16(v - __bfloat162float(h));
}
__device__ __forceinline__ void cpa16(u32 saddr, const void* g) {
    asm volatile("cp.async.cg.shared.global [%0], [%1], 16;" :: "r"(saddr), "l"(g) : "memory");
}
#define CPA_COMMIT() asm volatile("cp.async.commit_group;" ::: "memory")
#define CPA_WAIT1()  asm volatile("cp.async.wait_group 1;" ::: "memory")

__device__ __forceinline__ u32 tswz(int row, int lc) {
    return (u32)(row * 128 + ((lc ^ (row & 7)) << 4));
}
__device__ __forceinline__ void cpa_tile2(const bf* __restrict__ hi, const bf* __restrict__ lo,
                                          int rowMax, int r0, int tid, u32 sdst) {
#pragma unroll
    for (int i = 0; i < 4; i++) {
        int c = i * 256 + tid;
        int row = c >> 3;
        int lc  = c & 7;
        int m = r0 + row;
        if (m >= rowMax) m = rowMax - 1;
        const bf* src = (lc < 4) ? hi + (size_t)m * Hh + lc * 8
                                 : lo + (size_t)m * Hh + (lc - 4) * 8;
        cpa16(sdst + tswz(row, lc), src);
    }
}

__device__ __forceinline__ float fsig(float x)  { return 1.f / (1.f + __expf(-x)); }
__device__ __forceinline__ float ftanh(float x) { return 2.f / (1.f + __expf(-2.f * x)) - 1.f; }

__device__ __forceinline__ void atomicMaxF(float* a, float v) {
    if (v >= 0.f) atomicMax((int*)a, __float_as_int(v));
    else          atomicMin((unsigned int*)a, __float_as_uint(v));
}

// ============ shared GEMM body (FCMAX: reduce to column max instead of store) ============
template <bool FCMAX>
__device__ __forceinline__ void gemm_body(
    const bf* __restrict__ Ahi, const bf* __restrict__ Alo,
    const bf* __restrict__ Bhi, const bf* __restrict__ Blo,
    const float* __restrict__ bias, const float* __restrict__ bm,
    const int* __restrict__ deg,
    float* __restrict__ C, bf* __restrict__ outHi, bf* __restrict__ outLo,
    float* __restrict__ outMax,
    int M, int Nout, int nSeg, int m0, int n0, char* smem)
{
    const int tid = threadIdx.x;
    const int lane = tid & 31, wid = tid >> 5;
    const int wm = wid & 3, wn = wid >> 2;
    const int NKB = nSeg * 16;
    const bool msg = (nSeg > 1);
    u32 sb = smem_u32(smem);

    float acc[2][8][4];
#pragma unroll
    for (int i = 0; i < 2; i++)
#pragma unroll
        for (int j = 0; j < 8; j++)
#pragma unroll
            for (int k = 0; k < 4; k++) acc[i][j][k] = 0.f;

#pragma unroll
    for (int s = 0; s < 2; s++) {
        int tseg = s >> 4, koff = (s & 15) * 32;
        size_t ao = (size_t)tseg * ((size_t)Nn * Hh) + koff;
        size_t bo = (size_t)tseg * ((size_t)Hh * Hh) + koff;
        u32 dst = sb + s * BUFSZ;
        cpa_tile2(Ahi + ao, Alo + ao, M, m0, tid, dst);
        cpa_tile2(Bhi + bo, Blo + bo, 1 << 30, n0, tid, dst + TILE_SZ);
        CPA_COMMIT();
    }

    int buf = 0;
    for (int kb = 0; kb < NKB; kb++) {
        CPA_WAIT1();
        __syncthreads();

        if (kb + 2 < NKB) {
            int kn = kb + 2;
            int tseg = kn >> 4, koff = (kn & 15) * 32;
            size_t ao = (size_t)tseg * ((size_t)Nn * Hh) + koff;
            size_t bo = (size_t)tseg * ((size_t)Hh * Hh) + koff;
            int bn = buf + 2; if (bn >= NSTAGE) bn -= NSTAGE;
            u32 dst = sb + bn * BUFSZ;
            cpa_tile2(Ahi + ao, Alo + ao, M, m0, tid, dst);
            cpa_tile2(Bhi + bo, Blo + bo, 1 << 30, n0, tid, dst + TILE_SZ);
        }
        CPA_COMMIT();

        u32 aT = sb + buf * BUFSZ;
        u32 bT = aT + TILE_SZ;
#pragma unroll
        for (int ks = 0; ks < 2; ks++) {
            int lcA = 2 * ks + (lane >> 4);
            u32 ah[2][4], al[2][4];
#pragma unroll
            for (int mt = 0; mt < 2; mt++) {
                int row = wm * 32 + mt * 16 + (lane & 15);
                ldsm4(ah[mt], aT + tswz(row, lcA));
                ldsm4(al[mt], aT + tswz(row, lcA + 4));
            }
#pragma unroll
            for (int half = 0; half < 2; half++) {
                u32 bh[2][4], bl[2][4];
#pragma unroll
                for (int np = 0; np < 2; np++) {
                    int np2 = half * 2 + np;
                    int row = wn * 64 + np2 * 16 + (lane & 7) + ((lane >> 3) & 1) * 8;
                    ldsm4(bh[np], bT + tswz(row, lcA));
                    ldsm4(bl[np], bT + tswz(row, lcA + 4));
                }
#pragma unroll
                for (int mt = 0; mt < 2; mt++)
#pragma unroll
                    for (int j = 0; j < 4; j++) {
                        int np = j >> 1, sub = j & 1;
                        int nt = half * 4 + j;
                        mma16816(acc[mt][nt], ah[mt], bh[np][sub], bh[np][sub + 2]);
                        mma16816(acc[mt][nt], ah[mt], bl[np][sub], bl[np][sub + 2]);
                        mma16816(acc[mt][nt], al[mt], bh[np][sub], bh[np][sub + 2]);
                    }
            }
        }
        buf++; if (buf >= NSTAGE) buf = 0;
    }

    __syncthreads();

    if (FCMAX) {
        // per-thread column max over its valid rows, then shfl-reduce over row-lanes, then atomicMax
#pragma unroll
        for (int nt = 0; nt < 8; nt++) {
            float m0v = -INFINITY, m1v = -INFINITY;
#pragma unroll
            for (int mt = 0; mt < 2; mt++) {
                int rbase = m0 + wm * 32 + mt * 16 + (lane >> 2);
#pragma unroll
                for (int half = 0; half < 2; half++) {
                    int r = rbase + half * 8;
                    if (r >= M) continue;
                    m0v = fmaxf(m0v, acc[mt][nt][half * 2 + 0]);
                    m1v = fmaxf(m1v, acc[mt][nt][half * 2 + 1]);
                }
            }
#pragma unroll
            for (int d = 4; d < 32; d <<= 1) {
                m0v = fmaxf(m0v, __shfl_xor_sync(0xFFFFFFFFu, m0v, d));
                m1v = fmaxf(m1v, __shfl_xor_sync(0xFFFFFFFFu, m1v, d));
            }
            if ((lane >> 2) == 0) {
                int col = n0 + wn * 64 + nt * 8 + (lane & 3) * 2;
                float2 b = *reinterpret_cast<const float2*>(bias + col);
                atomicMaxF(outMax + col,     m0v + b.x);
                atomicMaxF(outMax + col + 1, m1v + b.y);
            }
        }
        return;
    }

    // ---- standard epilogue ----
#pragma unroll
    for (int mt = 0; mt < 2; mt++) {
        int rbase = m0 + wm * 32 + mt * 16 + (lane >> 2);
#pragma unroll
        for (int half = 0; half < 2; half++) {
            int r = rbase + half * 8;
            if (r >= M) continue;
            float dgv[Tt];
            if (msg) {
#pragma unroll
                for (int t = 0; t < Tt; t++) dgv[t] = (float)deg[t * Nn + r];
            }
#pragma unroll
            for (int nt = 0; nt < 8; nt++) {
                int col = n0 + wn * 64 + nt * 8 + (lane & 3) * 2;
                float v0 = acc[mt][nt][half * 2 + 0];
                float v1 = acc[mt][nt][half * 2 + 1];
                if (msg) {
#pragma unroll
                    for (int t = 0; t < Tt; t++) {
                        float2 b = *reinterpret_cast<const float2*>(bm + t * Hh + col);
                        v0 += dgv[t] * b.x;
                        v1 += dgv[t] * b.y;
                    }
                } else {
                    float2 b = *reinterpret_cast<const float2*>(bias + col);
                    v0 += b.x; v1 += b.y;
                }
                if (outHi) {
                    bf h0, l0, h1, l1;
                    split1(v0, h0, l0);
                    split1(v1, h1, l1);
                    size_t o = (size_t)r * Nout + col;
                    *reinterpret_cast<__nv_bfloat162*>(outHi + o) = __nv_bfloat162(h0, h1);
                    *reinterpret_cast<__nv_bfloat162*>(outLo + o) = __nv_bfloat162(l0, l1);
                } else {
                    *reinterpret_cast<float2*>(C + (size_t)r * Nout + col) = make_float2(v0, v1);
                }
            }
        }
    }
}

// gi GEMM
__global__ __launch_bounds__(256, 2)
void mma_gemm(const bf* __restrict__ Ahi, const bf* __restrict__ Alo,
              const bf* __restrict__ Bhi, const bf* __restrict__ Blo,
              const float* __restrict__ bias, const float* __restrict__ bm,
              const int* __restrict__ deg,
              float* __restrict__ C, bf* __restrict__ outHi, bf* __restrict__ outLo,
              int M, int Nout, int nSeg)
{
    extern __shared__ __align__(16) char smem[];
    gemm_body<false>(Ahi, Alo, Bhi, Blo, bias, bm, deg, C, outHi, outLo, nullptr,
                     M, Nout, nSeg, blockIdx.x * 128, blockIdx.y * 128, smem);
}

// fc GEMM with fused column-max
__global__ __launch_bounds__(256, 2)
void mma_fc_max(const bf* __restrict__ Ahi, const bf* __restrict__ Alo,
                const bf* __restrict__ Bhi, const bf* __restrict__ Blo,
                const float* __restrict__ bias, float* __restrict__ outMax)
{
    extern __shared__ __align__(16) char smem[];
    gemm_body<true>(Ahi, Alo, Bhi, Blo, bias, nullptr, nullptr,
                    nullptr, nullptr, nullptr, outMax,
                    Nn, Hh, 1, blockIdx.x * 128, blockIdx.y * 128, smem);
}

// dual launch: y<4 -> msg GEMM, y>=4 -> gh GEMM
__global__ __launch_bounds__(256, 2)
void mma_dual(const bf* __restrict__ Shi, const bf* __restrict__ Slo,
              const bf* __restrict__ Wmh, const bf* __restrict__ Wml,
              const float* __restrict__ bm, const int* __restrict__ deg,
              bf* __restrict__ iHi, bf* __restrict__ iLo,
              const bf* __restrict__ hhi, const bf* __restrict__ hlo,
              const bf* __restrict__ Whh, const bf* __restrict__ Whl,
              const float* __restrict__ bhh, float* __restrict__ gh)
{
    extern __shared__ __align__(16) char smem[];
    int y = blockIdx.y;
    if (y < 4) {
        gemm_body<false>(Shi, Slo, Wmh, Wml, nullptr, bm, deg,
                         nullptr, iHi, iLo, nullptr, Nn, Hh, Tt,
                         blockIdx.x * 128, y * 128, smem);
    } else {
        gemm_body<false>(hhi, hlo, Whh, Whl, bhh, nullptr, nullptr,
                         gh, nullptr, nullptr, nullptr, Nn, G3, 1,
                         blockIdx.x * 128, (y - 4) * 128, smem);
    }
}

// ---------------- fused init ----------------
__global__ void init_all(const float* __restrict__ x,
                         const float* __restrict__ W_msg, const float* __restrict__ W_ih,
                         const float* __restrict__ W_hh,  const float* __restrict__ fc_W,
                         float* __restrict__ h,
                         bf* __restrict__ hhi, bf* __restrict__ hlo,
                         bf* __restrict__ Wmh, bf* __restrict__ Wml,
                         bf* __restrict__ Wih, bf* __restrict__ Wil,
                         bf* __restrict__ Whh, bf* __restrict__ Whl,
                         bf* __restrict__ fch, bf* __restrict__ fcl,
                         float* __restrict__ outMax) {
    const int R0 = Nn * Hh / 4;
    const int R1 = R0 + WMSG_SZ / 4;
    const int R2 = R1 + WIH_SZ / 4;
    const int R3 = R2 + WIH_SZ / 4;
    const int R4 = R3 + FC_SZ / 4;
    int i = blockIdx.x * blockDim.x + threadIdx.x;
    if (i < Hh) outMax[i] = -INFINITY;
    int stride = gridDim.x * blockDim.x;
    for (; i < R4; i += stride) {
        const float* src; bf* hi; bf* lo; int k; bool cp = false;
        if (i < R0)      { src = x;     hi = hhi; lo = hlo; k = i;      cp = true; }
        else if (i < R1) { src = W_msg; hi = Wmh; lo = Wml; k = i - R0; }
        else if (i < R2) { src = W_ih;  hi = Wih; lo = Wil; k = i - R1; }
        else if (i < R3) { src = W_hh;  hi = Whh; lo = Whl; k = i - R2; }
        else             { src = fc_W;  hi = fch; lo = fcl; k = i - R3; }
        float4 v = reinterpret_cast<const float4*>(src)[k];
        if (cp) reinterpret_cast<float4*>(h)[k] = v;
        bf h0,l0,h1,l1,h2,l2,h3,l3;
        split1(v.x, h0, l0); split1(v.y, h1, l1);
        split1(v.z, h2, l2); split1(v.w, h3, l3);
        *reinterpret_cast<__nv_bfloat162*>(hi + k*4)     = __nv_bfloat162(h0, h1);
        *reinterpret_cast<__nv_bfloat162*>(hi + k*4 + 2) = __nv_bfloat162(h2, h3);
        *reinterpret_cast<__nv_bfloat162*>(lo + k*4)     = __nv_bfloat162(l0, l1);
        *reinterpret_cast<__nv_bfloat162*>(lo + k*4 + 2) = __nv_bfloat162(l2, l3);
    }
}

__global__ void zero2_i(int* p, int* q, int n) {
    int i = blockIdx.x * blockDim.x + threadIdx.x;
    if (i < n) { p[i] = 0; q[i] = 0; }
}
__global__ void count_deg(const int* __restrict__ edges, int* __restrict__ deg) {
    int idx = blockIdx.x * blockDim.x + threadIdx.x;
    if (idx < Tt * Ee) {
        int t = idx / Ee;
        int tgt = edges[idx * 2 + 1];
        atomicAdd(&deg[t * Nn + tgt], 1);
    }
}

// ---------------- CSR build ----------------
__global__ void scan1(const int* __restrict__ deg, int* __restrict__ off, int* __restrict__ bsum) {
    __shared__ int sm[1024];
    int t = threadIdx.x;
    int i = blockIdx.x * 1024 + t;
    int v = (i < TN) ? deg[i] : 0;
    sm[t] = v;
    __syncthreads();
    for (int d = 1; d < 1024; d <<= 1) {
        int x = (t >= d) ? sm[t - d] : 0;
        __syncthreads();
        sm[t] += x;
        __syncthreads();
    }
    if (i < TN) off[i + 1] = sm[t];
    if (t == 1023) bsum[blockIdx.x] = sm[t];
}
__global__ void scan2(const int* __restrict__ bsum, int* __restrict__ bofs, int nb) {
    __shared__ int sm[64];
    int t = threadIdx.x;
    int v = (t < nb) ? bsum[t] : 0;
    sm[t] = v;
    __syncthreads();
    for (int d = 1; d < 64; d <<= 1) {
        int x = (t >= d) ? sm[t - d] : 0;
        __syncthreads();
        sm[t] += x;
        __syncthreads();
    }
    bofs[t] = sm[t] - v;
}
__global__ void scan3(int* __restrict__ off, const int* __restrict__ bofs) {
    int i = blockIdx.x * blockDim.x + threadIdx.x;
    if (i == 0) off[0] = 0;
    if (i < TN) off[i + 1] += bofs[i >> 10];
}
__global__ void scatter_csr(const int* __restrict__ edges, const int* __restrict__ off,
                            int* __restrict__ cur, int* __restrict__ csr) {
    int idx = blockIdx.x * blockDim.x + threadIdx.x;
    if (idx >= Tt * Ee) return;
    int t = idx / Ee;
    int src = edges[idx * 2 + 0];
    int tgt = edges[idx * 2 + 1];
    int r = t * Nn + tgt;
    int p = off[r] + atomicAdd(&cur[r], 1);
    csr[p] = src;
}

// ---------------- CSR aggregation -> bf16 hi/lo S (4-edge unroll) ----------------
__device__ __forceinline__ void st4_split(bf* hi, bf* lo, float4 a) {
    bf h0,l0,h1,l1,h2,l2,h3,l3;
    split1(a.x, h0, l0); split1(a.y, h1, l1);
    split1(a.z, h2, l2); split1(a.w, h3, l3);
    *reinterpret_cast<__nv_bfloat162*>(hi)     = __nv_bfloat162(h0, h1);
    *reinterpret_cast<__nv_bfloat162*>(hi + 2) = __nv_bfloat162(h2, h3);
    *reinterpret_cast<__nv_bfloat162*>(lo)     = __nv_bfloat162(l0, l1);
    *reinterpret_cast<__nv_bfloat162*>(lo + 2) = __nv_bfloat162(l2, l3);
}
__device__ __forceinline__ void acc4(float4& a, float4 v) {
    a.x += v.x; a.y += v.y; a.z += v.z; a.w += v.w;
}
__global__ void agg_csr(const float* __restrict__ h, const int* __restrict__ csr,
                        const int* __restrict__ off, bf* __restrict__ Shi,
                        bf* __restrict__ Slo) {
    int row = (blockIdx.x * blockDim.x + threadIdx.x) >> 5;
    int lane = threadIdx.x & 31;
    if (row >= TN) return;
    int s = off[row], e = off[row + 1];
    float4 a0 = make_float4(0.f,0.f,0.f,0.f), a1 = a0, a2 = a0, a3 = a0;
    int i = s;
    for (; i + 4 <= e; i += 4) {
        const float4* p0 = reinterpret_cast<const float4*>(h + (size_t)__ldg(csr + i)     * Hh);
        const float4* p1 = reinterpret_cast<const float4*>(h + (size_t)__ldg(csr + i + 1) * Hh);
        const float4* p2 = reinterpret_cast<const float4*>(h + (size_t)__ldg(csr + i + 2) * Hh);
        const float4* p3 = reinterpret_cast<const float4*>(h + (size_t)__ldg(csr + i + 3) * Hh);
        acc4(a0, p0[lane]);    acc4(a0, p1[lane]);    acc4(a0, p2[lane]);    acc4(a0, p3[lane]);
        acc4(a1, p0[lane+32]); acc4(a1, p1[lane+32]); acc4(a1, p2[lane+32]); acc4(a1, p3[lane+32]);
        acc4(a2, p0[lane+64]); acc4(a2, p1[lane+64]); acc4(a2, p2[lane+64]); acc4(a2, p3[lane+64]);
        acc4(a3, p0[lane+96]); acc4(a3, p1[lane+96]); acc4(a3, p2[lane+96]); acc4(a3, p3[lane+96]);
    }
    for (; i < e; i++) {
        const float4* p0 = reinterpret_cast<const float4*>(h + (size_t)__ldg(csr + i) * Hh);
        acc4(a0, p0[lane]); acc4(a1, p0[lane + 32]);
        acc4(a2, p0[lane + 64]); acc4(a3, p0[lane + 96]);
    }
    bf* Hp = Shi + (size_t)row * Hh;
    bf* Lp = Slo + (size_t)row * Hh;
    st4_split(Hp + lane * 4,         Lp + lane * 4,         a0);
    st4_split(Hp + (lane + 32) * 4,  Lp + (lane + 32) * 4,  a1);
    st4_split(Hp + (lane + 64) * 4,  Lp + (lane + 64) * 4,  a2);
    st4_split(Hp + (lane + 96) * 4,  Lp + (lane + 96) * 4,  a3);
}

// ---------------- GRU elementwise ----------------
__global__ void gru_kernel(const float* __restrict__ gi, const float* __restrict__ gh,
                           const float* __restrict__ h, float* __restrict__ hout,
                           bf* __restrict__ hhi, bf* __restrict__ hlo) {
    int idx4 = blockIdx.x * blockDim.x + threadIdx.x;
    if (idx4 >= Nn * Hh / 4) return;
    int n = idx4 >> 7;
    int j4 = idx4 & 127;
    size_t base = ((size_t)n * G3 + j4 * 4) >> 2;
    const float4* gi4 = reinterpret_cast<const float4*>(gi);
    const float4* gh4 = reinterpret_cast<const float4*>(gh);
    float4 ir = gi4[base],        hr = gh4[base];
    float4 iz = gi4[base + 128],  hz = gh4[base + 128];
    float4 in_ = gi4[base + 256], hn = gh4[base + 256];
    float4 hv = reinterpret_cast<const float4*>(h)[idx4];
    float o[4];
    float irA[4] = {ir.x, ir.y, ir.z, ir.w}, hrA[4] = {hr.x, hr.y, hr.z, hr.w};
    float izA[4] = {iz.x, iz.y, iz.z, iz.w}, hzA[4] = {hz.x, hz.y, hz.z, hz.w};
    float inA[4] = {in_.x, in_.y, in_.z, in_.w}, hnA[4] = {hn.x, hn.y, hn.z, hn.w};
    float hA[4]  = {hv.x, hv.y, hv.z, hv.w};
#pragma unroll
    for (int q = 0; q < 4; q++) {
        float r = fsig(irA[q] + hrA[q]);
        float z = fsig(izA[q] + hzA[q]);
        float nv = ftanh(inA[q] + r * hnA[q]);
        o[q] = (1.f - z) * nv + z * hA[q];
    }
    reinterpret_cast<float4*>(hout)[idx4] = make_float4(o[0], o[1], o[2], o[3]);
    bf h0,l0,h1,l1,h2,l2,h3,l3;
    split1(o[0], h0, l0); split1(o[1], h1, l1);
    split1(o[2], h2, l2); split1(o[3], h3, l3);
    *reinterpret_cast<__nv_bfloat162*>(hhi + idx4*4)     = __nv_bfloat162(h0, h1);
    *reinterpret_cast<__nv_bfloat162*>(hhi + idx4*4 + 2) = __nv_bfloat162(h2, h3);
    *reinterpret_cast<__nv_bfloat162*>(hlo + idx4*4)     = __nv_bfloat162(l0, l1);
    *reinterpret_cast<__nv_bfloat162*>(hlo + idx4*4 + 2) = __nv_bfloat162(l2, l3);
}

// ---------------- launch ----------------
extern "C" void kernel_launch(void* const* d_in, const int* in_sizes, int n_in,
                              void* d_out, int out_size) {
    const float* x     = (const float*)d_in[0];
    const int*   edges = (const int*)  d_in[1];
    const float* W_msg = (const float*)d_in[2];
    const float* b_msg = (const float*)d_in[3];
    const float* W_ih  = (const float*)d_in[4];
    const float* W_hh  = (const float*)d_in[5];
    const float* b_ih  = (const float*)d_in[6];
    const float* b_hh  = (const float*)d_in[7];
    const float* fc_W  = (const float*)d_in[8];
    const float* fc_b  = (const float*)d_in[9];
    float* out = (float*)d_out;

    float *ph, *pgi, *pgh;
    bf *pShi, *pSlo, *pihi, *pilo, *phhi, *phlo;
    bf *pWmh, *pWml, *pWih, *pWil, *pWhh, *pWhl, *pfch, *pfcl;
    int *pdeg, *poff, *pcur, *pcsr, *pbsum, *pbofs;
    cudaGetSymbolAddress((void**)&ph,    g_h);
    cudaGetSymbolAddress((void**)&pgi,   g_gi);
    cudaGetSymbolAddress((void**)&pgh,   g_gh);
    cudaGetSymbolAddress((void**)&pShi,  g_Shi);
    cudaGetSymbolAddress((void**)&pSlo,  g_Slo);
    cudaGetSymbolAddress((void**)&pihi,  g_ihi);
    cudaGetSymbolAddress((void**)&pilo,  g_ilo);
    cudaGetSymbolAddress((void**)&phhi,  g_hhi);
    cudaGetSymbolAddress((void**)&phlo,  g_hlo);
    cudaGetSymbolAddress((void**)&pWmh,  g_Wmh);
    cudaGetSymbolAddress((void**)&pWml,  g_Wml);
    cudaGetSymbolAddress((void**)&pWih,  g_Wih);
    cudaGetSymbolAddress((void**)&pWil,  g_Wil);
    cudaGetSymbolAddress((void**)&pWhh,  g_Whh);
    cudaGetSymbolAddress((void**)&pWhl,  g_Whl);
    cudaGetSymbolAddress((void**)&pfch,  g_fch);
    cudaGetSymbolAddress((void**)&pfcl,  g_fcl);
    cudaGetSymbolAddress((void**)&pdeg,  g_deg);
    cudaGetSymbolAddress((void**)&poff,  g_off);
    cudaGetSymbolAddress((void**)&pcur,  g_cur);
    cudaGetSymbolAddress((void**)&pcsr,  g_csr);
    cudaGetSymbolAddress((void**)&pbsum, g_bsum);
    cudaGetSymbolAddress((void**)&pbofs, g_bofs);

    cudaFuncSetAttribute(mma_gemm,   cudaFuncAttributeMaxDynamicSharedMemorySize, SMEM_BYTES);
    cudaFuncSetAttribute(mma_dual,   cudaFuncAttributeMaxDynamicSharedMemorySize, SMEM_BYTES);
    cudaFuncSetAttribute(mma_fc_max, cudaFuncAttributeMaxDynamicSharedMemorySize, SMEM_BYTES);

    float* hc = ph;
    float* hn = ph + (size_t)Nn * Hh;

    init_all<<<4096, 256>>>(x, W_msg, W_ih, W_hh, fc_W, hc,
                            phhi, phlo, pWmh, pWml, pWih, pWil, pWhh, pWhl, pfch, pfcl,
                            out);

    zero2_i<<<(TN + 255) / 256, 256>>>(pdeg, pcur, TN);
    count_deg<<<(Tt * Ee + 255) / 256, 256>>>(edges, pdeg);
    scan1<<<(TN + 1023) / 1024, 1024>>>(pdeg, poff, pbsum);
    scan2<<<1, 64>>>(pbsum, pbofs, (TN + 1023) / 1024);
    scan3<<<(TN + 255) / 256, 256>>>(poff, pbofs);
    scatter_csr<<<(Tt * Ee + 255) / 256, 256>>>(edges, poff, pcur, pcsr);

    dim3 gFc(MBLK, Hh / 128);   // 79 x 4
    dim3 gd(MBLK, 16);          // 79 x 16 (msg + gh dual)
    dim3 gg(MBLK, G3 / 128);    // 79 x 12 (gi)
    int aggBlocks = (TN * 32 + 255) / 256;

    for (int layer = 0; layer < Ll; layer++) {
        const bf* Wmh_l = pWmh + (size_t)layer * Tt * Hh * Hh;
        const bf* Wml_l = pWml + (size_t)layer * Tt * Hh * Hh;
        const bf* Wih_l = pWih + (size_t)layer * G3 * Hh;
        const bf* Wil_l = pWil + (size_t)layer * G3 * Hh;
        const bf* Whh_l = pWhh + (size_t)layer * G3 * Hh;
        const bf* Whl_l = pWhl + (size_t)layer * G3 * Hh;
        const float* bm_l  = b_msg + (size_t)layer * Tt * Hh;
        const float* bih_l = b_ih  + (size_t)layer * G3;
        const float* bhh_l = b_hh  + (size_t)layer * G3;
        for (int s = 0; s < 2; s++) {
            agg_csr<<<aggBlocks, 256>>>(hc, pcsr, poff, pShi, pSlo);
            mma_dual<<<gd, 256, SMEM_BYTES>>>(pShi, pSlo, Wmh_l, Wml_l, bm_l, pdeg,
                                              pihi, pilo,
                                              phhi, phlo, Whh_l, Whl_l, bhh_l, pgh);
            mma_gemm<<<gg, 256, SMEM_BYTES>>>(pihi, pilo, Wih_l, Wil_l,
                                              bih_l, nullptr, nullptr,
                                              pgi, nullptr, nullptr, Nn, G3, 1);
            gru_kernel<<<(Nn * Hh / 4 + 255) / 256, 256>>>(pgi, pgh, hc, hn, phhi, phlo);
            float* t = hc; hc = hn; hn = t;
        }
    }

    // fc GEMM with fused global column-max (out pre-initialized to -inf in init_all)
    mma_fc_max<<<gFc, 256, SMEM_BYTES>>>(phhi, phlo, pfch, pfcl, fc_b, out);
}